// round 15
// baseline (speedup 1.0000x reference)
#include <cuda_runtime.h>
#include <math.h>

#define HH 512
#define NN 64
#define LL 4096
#define MM 2048
#define LF 2049
#define TBLK 2560          // 2048 cauchy-role + 512 fft-role blocks
// interleave mapping: lag of 160 heads (~1 wave) between Cauchy(h) and FFT(h)
#define LAGH 160
#define SEG0 (4 * LAGH)                 // 640: pure-cauchy prefix
#define SEG1 (SEG0 + 5 * (HH - LAGH))   // 2400: interleaved groups of 5

typedef unsigned long long ull;

__device__ float2 g_X[HH * LF];   // Cauchy spectrum X[h][l], l=0..2048
__device__ float2 g_tw[1025];     // exp(+i*pi*j/2048), j=0..1024
__device__ int    g_done[HH];     // per-head completion count (reset by FFT role)
__device__ int    g_twdone;       // twiddle-publish count (monotone; values idempotent)

__device__ __forceinline__ ull f2_fma(ull a, ull b, ull c) {
    ull d; asm("fma.rn.f32x2 %0, %1, %2, %3;" : "=l"(d) : "l"(a), "l"(b), "l"(c)); return d;
}
__device__ __forceinline__ ull f2_mul(ull a, ull b) {
    ull d; asm("mul.rn.f32x2 %0, %1, %2;" : "=l"(d) : "l"(a), "l"(b)); return d;
}
__device__ __forceinline__ ull f2_add(ull a, ull b) {
    ull d; asm("add.rn.f32x2 %0, %1, %2;" : "=l"(d) : "l"(a), "l"(b)); return d;
}
__device__ __forceinline__ ull f2_pack(float lo, float hi) {
    ull d; asm("mov.b64 %0, {%1, %2};" : "=l"(d) : "f"(lo), "f"(hi)); return d;
}
__device__ __forceinline__ float2 f2_unpack(ull a) {
    float lo, hi; asm("mov.b64 {%0, %1}, %2;" : "=f"(lo), "=f"(hi) : "l"(a));
    return make_float2(lo, hi);
}
__device__ __forceinline__ float frcp(float x) {
    float r; asm("rcp.approx.f32 %0, %1;" : "=f"(r) : "f"(x)); return r;
}

// complex helpers
__device__ __forceinline__ float2 cmul(float2 a, float2 b) {
    return make_float2(a.x * b.x - a.y * b.y, a.x * b.y + a.y * b.x);
}
__device__ __forceinline__ float2 csq(float2 a) {
    return make_float2(a.x * a.x - a.y * a.y, 2.0f * a.x * a.y);
}
__device__ __forceinline__ float2 cadd(float2 a, float2 b) { return make_float2(a.x + b.x, a.y + b.y); }
__device__ __forceinline__ float2 csub(float2 a, float2 b) { return make_float2(a.x - b.x, a.y - b.y); }
__device__ __forceinline__ float2 cmuli(float2 a) { return make_float2(-a.y, a.x); }

#define IDX(i) ((i) + ((i) >> 3))
#define R2C 0.70710678118654752f

__device__ __forceinline__ void radix8_pass(float2* spec, const float2* tw, int tid, int s) {
    const int hh   = 1 << (s - 1);
    const int j    = tid & (hh - 1);
    const int base = ((tid >> (s - 1)) << (s + 2)) + j;

    float2 x[8];
    #pragma unroll
    for (int q = 0; q < 8; q++) x[q] = spec[IDX(base + q * hh)];

    const float2 w4 = tw[j << (10 - s)];   // W_M^(j*2^(9-s))
    const float2 w2 = csq(w4);
    const float2 w1 = csq(w2);

    float2 a[8];
    #pragma unroll
    for (int p = 0; p < 4; p++) {
        const float2 t = cmul(w1, x[2 * p + 1]);
        a[2 * p]     = cadd(x[2 * p], t);
        a[2 * p + 1] = csub(x[2 * p], t);
    }
    float2 b[8];
    #pragma unroll
    for (int g = 0; g < 2; g++) {
        const int o = 4 * g;
        const float2 t2 = cmul(w2, a[o + 2]);
        const float2 t3 = cmuli(cmul(w2, a[o + 3]));
        b[o + 0] = cadd(a[o + 0], t2);
        b[o + 2] = csub(a[o + 0], t2);
        b[o + 1] = cadd(a[o + 1], t3);
        b[o + 3] = csub(a[o + 1], t3);
    }
    const float2 u  = make_float2(R2C, R2C);
    const float2 vu = cmul(w4, u);
    const float2 t4 = cmul(w4, b[4]);
    const float2 t5 = cmul(vu, b[5]);
    const float2 t6 = cmul(cmuli(w4), b[6]);
    const float2 t7 = cmul(cmuli(vu), b[7]);

    spec[IDX(base + 0 * hh)] = cadd(b[0], t4);
    spec[IDX(base + 4 * hh)] = csub(b[0], t4);
    spec[IDX(base + 1 * hh)] = cadd(b[1], t5);
    spec[IDX(base + 5 * hh)] = csub(b[1], t5);
    spec[IDX(base + 2 * hh)] = cadd(b[2], t6);
    spec[IDX(base + 6 * hh)] = csub(b[2], t6);
    spec[IDX(base + 3 * hh)] = cadd(b[3], t7);
    spec[IDX(base + 7 * hh)] = csub(b[3], t7);
}

// ============================================================================
// Fused kernel, interleaved placement. grid TBLK, block 256.
//   bid < SEG0:           Cauchy, h = bid>>2, quarter = bid&3   (heads 0..159)
//   SEG0 <= bid < SEG1:   groups of 5: 4x Cauchy(head 160+grp) + 1x FFT(head grp)
//   bid >= SEG1:          FFT, h = (HH-LAGH) + (bid - SEG1)     (heads 352..511)
// FFT(h) spin-waits for done[h]==4 (fence-ordered), then resets done[h].
// ============================================================================
__global__ __launch_bounds__(256, 4) void s4_fused(
    const float* __restrict__ A_real,
    const float* __restrict__ A_imag,
    const float* __restrict__ Bm,
    const float* __restrict__ Cm,
    const float* __restrict__ Pm,
    const float* __restrict__ inv_dt,
    float* __restrict__ out)
{
    __shared__ __align__(16) char smraw[(2305 + 1025) * 8];   // 26.6 KB union

    const int bid = blockIdx.x;
    const int tid = threadIdx.x;
    const float ANG = 3.14159265358979323846f / 4096.0f;

    // ---- bid -> (role, h, quarter) ----
    bool is_cauchy;
    int h, quarter = 0;
    if (bid < SEG0) {
        is_cauchy = true;  h = bid >> 2;  quarter = bid & 3;
    } else if (bid < SEG1) {
        const int g   = bid - SEG0;
        const int grp = g / 5;
        const int r   = g - 5 * grp;
        if (r < 4) { is_cauchy = true;  h = LAGH + grp;  quarter = r; }
        else       { is_cauchy = false; h = grp; }
    } else {
        is_cauchy = false;  h = (HH - LAGH) + (bid - SEG1);
    }

    if (is_cauchy) {
        // ==================== Cauchy role ====================
        ulonglong2 (*s_coef)[9] = (ulonglong2(*)[9])smraw;

        if (bid < 5) {   // publish twiddles (idempotent every call)
            const int j = bid * 256 + tid;
            if (j <= 1024) {
                float s, c;
                sincosf((float)j * (3.14159265358979323846f / 2048.0f), &s, &c);
                g_tw[j] = make_float2(c, s);
            }
        }

        if (tid < NN) {
            const int n  = tid;
            const float dt = expf(inv_dt[h]);
            const float ar = -expf(A_real[h * NN + n]) * dt;
            const float ai =  A_imag[h * NN + n] * dt;

            const int base = (h * NN + n) * 2;
            const float bx = Bm[base], by = Bm[base + 1];
            const float cx = Cm[base], cy = Cm[base + 1];
            const float px = Pm[base], py = Pm[base + 1];

            float vr[4], vi[4];
            vr[0] = (bx * cx - by * cy) * dt;  vi[0] = (bx * cy + by * cx) * dt;
            vr[1] = (bx * px + by * py) * dt;  vi[1] = (by * px - bx * py) * dt;
            vr[2] = (px * cx - py * cy) * dt;  vi[2] = (px * cy + py * cx) * dt;
            vr[3] = (px * px + py * py) * dt;  vi[3] = 0.0f;

            float* c = (float*)&s_coef[n >> 1][0];
            const int o = n & 1;
            const float ccoef = -2.0f * ar;
            const float m  = ar * ar + ai * ai;
            c[0 + o] = m;                              // m
            c[2 + o] = ccoef * ccoef;                  // c^2
            #pragma unroll
            for (int ab = 0; ab < 4; ab++) {
                const float p   = -2.0f * (vr[ab] * ar + vi[ab] * ai);
                const float q   =  2.0f * vr[ab];
                const float qc  = q * ccoef;
                const float npc = -p * ccoef;
                const int bo = 4 + ab * 8;
                c[bo + 0 + o] = p * m;                 // pm
                c[bo + 2 + o] = qc - p;                // qcp
                c[bo + 4 + o] = q * m + npc;           // qmnpc
                c[bo + 6 + o] = q;                     // q
            }
        }
        __syncthreads();

        const int base_l = quarter * 512 + tid;

        float yv[2];
        ull y2v[2], ny2v[2];
        #pragma unroll
        for (int b = 0; b < 2; b++) {
            const float ang = (float)(base_l + b * 256) * ANG;
            float s_, c_;
            __sincosf(ang, &s_, &c_);
            const float y = 2.0f * s_ * frcp(c_);      // fast tan (MUFU path)
            yv[b] = y;
            y2v[b]  = f2_pack(y * y, y * y);
            ny2v[b] = y2v[b] ^ 0x8000000080000000ULL;
        }

        ull accr[2][4], acci[2][4];
        #pragma unroll
        for (int b = 0; b < 2; b++)
            #pragma unroll
            for (int ab = 0; ab < 4; ab++) { accr[b][ab] = 0; acci[b][ab] = 0; }

        #pragma unroll 4
        for (int k = 0; k < NN / 2; k++) {
            const ulonglong2* cc = &s_coef[k][0];
            const ulonglong2 c0 = cc[0];               // (m, c2)

            ull invv[2];
            #pragma unroll
            for (int b = 0; b < 2; b++) {
                const ull dr  = f2_add(c0.x, ny2v[b]);                 // m - y2
                const ull mag = f2_fma(dr, dr, f2_mul(c0.y, y2v[b]));  // dr^2 + c2*y2
                const float2 m = f2_unpack(mag);
                invv[b] = f2_pack(frcp(m.x), frcp(m.y));
            }

            #pragma unroll
            for (int ab = 0; ab < 4; ab++) {
                const ulonglong2 ca = cc[1 + 2 * ab];  // (pm, qcp)
                const ulonglong2 cb = cc[2 + 2 * ab];  // (qmnpc, q)
                #pragma unroll
                for (int b = 0; b < 2; b++) {
                    const ull rt  = f2_fma(y2v[b],  ca.y, ca.x);   // pm + y2*qcp
                    const ull it2 = f2_fma(ny2v[b], cb.y, cb.x);   // qmnpc - y2*q
                    accr[b][ab] = f2_fma(rt,  invv[b], accr[b][ab]);
                    acci[b][ab] = f2_fma(it2, invv[b], acci[b][ab]);
                }
            }
        }

        #pragma unroll
        for (int b = 0; b < 2; b++) {
            const float y = yv[b];
            const int   l = base_l + b * 256;
            const float2 sr0 = f2_unpack(accr[b][0]), si0 = f2_unpack(acci[b][0]);
            const float2 sr1 = f2_unpack(accr[b][1]), si1 = f2_unpack(acci[b][1]);
            const float2 sr2 = f2_unpack(accr[b][2]), si2 = f2_unpack(acci[b][2]);
            const float2 sr3 = f2_unpack(accr[b][3]), si3 = f2_unpack(acci[b][3]);
            const float r00r = sr0.x + sr0.y, r00i = (si0.x + si0.y) * y;
            const float r01r = sr1.x + sr1.y, r01i = (si1.x + si1.y) * y;
            const float r10r = sr2.x + sr2.y, r10i = (si2.x + si2.y) * y;
            const float r11r = sr3.x + sr3.y, r11i = (si3.x + si3.y) * y;

            const float cr = 1.0f + r11r, ci = r11i;
            const float cinv = frcp(cr * cr + ci * ci);
            const float trm = r01r * r10r - r01i * r10i;
            const float tim = r01r * r10i + r01i * r10r;
            const float qr = (trm * cr + tim * ci) * cinv;
            const float qi = (tim * cr - trm * ci) * cinv;
            const float kr = r00r - qr;
            const float ki = r00i - qi;
            const float hy = 0.5f * y;
            float fr = kr - ki * hy;
            float fi = ki + kr * hy;
            if (l == 0) fi = 0.0f;
            g_X[h * LF + l] = make_float2(fr, fi);
        }

        if (quarter == 3 && tid == 0) {
            const float y  = 2.0f * tanf(2048.0f * ANG);
            const float y2 = y * y;
            float rr[4] = {0, 0, 0, 0}, riy[4] = {0, 0, 0, 0};
            for (int n = 0; n < NN; n++) {
                const float* c = (const float*)&s_coef[n >> 1][0];
                const int o = n & 1;
                const float dr = c[0 + o] - y2;
                const float inv = frcp(dr * dr + c[2 + o] * y2);
                #pragma unroll
                for (int ab = 0; ab < 4; ab++) {
                    const int bo = 4 + ab * 8;
                    rr[ab]  += (c[bo + 0 + o] + y2 * c[bo + 2 + o]) * inv;
                    riy[ab] += (c[bo + 4 + o] - y2 * c[bo + 6 + o]) * inv;
                }
            }
            const float r00r = rr[0];
            const float r01r = rr[1], r01i = riy[1] * y;
            const float r10r = rr[2], r10i = riy[2] * y;
            const float r11r = rr[3], r11i = riy[3] * y;
            const float cr = 1.0f + r11r, ci = r11i;
            const float cinv = frcp(cr * cr + ci * ci);
            const float trm = r01r * r10r - r01i * r10i;
            const float tim = r01r * r10i + r01i * r10r;
            const float qr = (trm * cr + tim * ci) * cinv;
            const float qi = (tim * cr - trm * ci) * cinv;
            const float kr = r00r - qr;
            const float ki = riy[0] * y - qi;
            const float fr = kr - ki * (0.5f * y);
            g_X[h * LF + 2048] = make_float2(fr, 0.0f);
        }

        // publish completion: all block stores visible, then count up
        __syncthreads();
        if (tid == 0) {
            __threadfence();
            atomicAdd(&g_done[h], 1);
            if (bid < 5) atomicAdd(&g_twdone, 1);
        }
    } else {
        // ==================== FFT role ====================
        float2* buf = (float2*)smraw;                       // 2305 float2
        float2* tw  = (float2*)(smraw + 2305 * 8);          // 1025 float2

        // wait for this head's spectrum + the twiddle table
        if (tid == 0) {
            int d, t;
            for (;;) {
                asm volatile("ld.acquire.gpu.global.b32 %0, [%1];" : "=r"(d) : "l"(&g_done[h]) : "memory");
                asm volatile("ld.acquire.gpu.global.b32 %0, [%1];" : "=r"(t) : "l"(&g_twdone)  : "memory");
                if (d >= 4 && t >= 5) break;
                __nanosleep(128);
            }
            // reset for next graph replay (replays are serialized)
            asm volatile("st.relaxed.gpu.global.b32 [%0], %1;" :: "l"(&g_done[h]), "r"(0) : "memory");
        }
        __syncthreads();

        const float2* Xh = &g_X[h * LF];
        #pragma unroll
        for (int m = 0; m < 8; m++) {
            const int i = tid + m * 256;
            buf[IDX(i)] = Xh[i];
        }
        if (tid == 0) buf[IDX(2048)] = Xh[2048];
        for (int j = tid; j <= 1024; j += 256) tw[j] = g_tw[j];
        __syncthreads();

        // gather X (bit-reversed), build Z, in-register radix-8 (stages 1-3)
        {
            const int rv = __brev(tid) >> 24;             // rev8(tid)
            float2 c[8];
            #pragma unroll
            for (int q = 0; q < 8; q++) {
                const int rq = (q == 0) ? 0 : (q == 1) ? 4 : (q == 2) ? 2 : (q == 3) ? 6
                             : (q == 4) ? 1 : (q == 5) ? 5 : (q == 6) ? 3 : 7;   // rev3(q)
                const int k  = rq * 256 + rv;
                const float2 Xk = buf[IDX(k)];
                const float2 Xm = buf[IDX(2048 - k)];
                float2 w;
                if (k <= 1024) w = tw[k];
                else { const float2 t = tw[k - 1024]; w = make_float2(-t.y, t.x); }
                const float arr = Xk.x + Xm.x, aii = Xk.y - Xm.y;
                const float brr = Xk.x - Xm.x, bii = Xk.y + Xm.y;
                c[q] = make_float2(arr - (w.x * bii + w.y * brr),
                                   aii + (w.x * brr - w.y * bii));
            }
            float2 a[8];
            #pragma unroll
            for (int p = 0; p < 4; p++) {
                a[2 * p]     = cadd(c[2 * p], c[2 * p + 1]);
                a[2 * p + 1] = csub(c[2 * p], c[2 * p + 1]);
            }
            float2 b[8];
            #pragma unroll
            for (int g = 0; g < 2; g++) {
                const int o = 4 * g;
                const float2 t3 = cmuli(a[o + 3]);
                b[o + 0] = cadd(a[o + 0], a[o + 2]);
                b[o + 2] = csub(a[o + 0], a[o + 2]);
                b[o + 1] = cadd(a[o + 1], t3);
                b[o + 3] = csub(a[o + 1], t3);
            }
            const float2 t4 = b[4];
            const float2 t5 = make_float2(R2C * (b[5].x - b[5].y), R2C * (b[5].x + b[5].y));
            const float2 t6 = cmuli(b[6]);
            const float2 t7 = make_float2(-R2C * (b[7].x + b[7].y), R2C * (b[7].x - b[7].y));

            __syncthreads();    // everyone done READING buf before overwriting it

            const int p0 = 8 * tid;
            buf[IDX(p0 + 0)] = cadd(b[0], t4);
            buf[IDX(p0 + 4)] = csub(b[0], t4);
            buf[IDX(p0 + 1)] = cadd(b[1], t5);
            buf[IDX(p0 + 5)] = csub(b[1], t5);
            buf[IDX(p0 + 2)] = cadd(b[2], t6);
            buf[IDX(p0 + 6)] = csub(b[2], t6);
            buf[IDX(p0 + 3)] = cadd(b[3], t7);
            buf[IDX(p0 + 7)] = csub(b[3], t7);
        }
        __syncthreads();

        radix8_pass(buf, tw, tid, 4);    // stages 4,5,6
        __syncthreads();
        radix8_pass(buf, tw, tid, 7);    // stages 7,8,9
        __syncthreads();

        // stages 10,11: fused radix-4, 512 butterflies, 2 per thread
        #pragma unroll
        for (int m = 0; m < 2; m++) {
            const int j = tid + m * 256;
            const float2 w2 = tw[2 * j];          // W_M^j
            const float2 w1 = csq(w2);
            const float2 x0 = buf[IDX(j)];
            const float2 x1 = buf[IDX(j + 512)];
            const float2 x2 = buf[IDX(j + 1024)];
            const float2 x3 = buf[IDX(j + 1536)];
            const float2 t1 = cmul(w1, x1);
            const float2 a0 = cadd(x0, t1), a1 = csub(x0, t1);
            const float2 t3 = cmul(w1, x3);
            const float2 a2 = cadd(x2, t3), a3 = csub(x2, t3);
            const float2 t2 = cmul(w2, a2);
            const float2 c3 = cmuli(cmul(w2, a3));
            buf[IDX(j)]        = cadd(a0, t2);
            buf[IDX(j + 1024)] = csub(a0, t2);
            buf[IDX(j + 512)]  = cadd(a1, c3);
            buf[IDX(j + 1536)] = csub(a1, c3);
        }
        __syncthreads();

        float2* out2 = (float2*)(out + h * LL);
        const float scale = 1.0f / (float)LL;
        #pragma unroll
        for (int m = 0; m < 8; m++) {
            const int n = tid + m * 256;
            const float2 z = buf[IDX(n)];
            out2[n] = make_float2(z.x * scale, z.y * scale);
        }
    }
}

extern "C" void kernel_launch(void* const* d_in, const int* in_sizes, int n_in,
                              void* d_out, int out_size)
{
    (void)in_sizes; (void)n_in; (void)out_size;
    s4_fused<<<TBLK, 256>>>(
        (const float*)d_in[0],   // A_real (H, N)
        (const float*)d_in[1],   // A_imag (H, N)
        (const float*)d_in[2],   // B (1, H, N, 2)
        (const float*)d_in[3],   // C (1, H, N, 2)
        (const float*)d_in[4],   // P (1, H, N, 2)
        (const float*)d_in[5],   // inv_dt (H,)
        (float*)d_out);          // (1, H, L) fp32
}

// round 16
// speedup vs baseline: 1.0513x; 1.0513x over previous
#include <cuda_runtime.h>
#include <math.h>

#define HH 512
#define NN 64
#define LL 4096
#define MM 2048
#define LF 2049

typedef unsigned long long ull;

__device__ float2 g_X[HH * LF];   // Cauchy spectrum X[h][l], l=0..2048
__device__ float2 g_tw[1025];     // exp(+i*pi*j/2048), j=0..1024

__device__ __forceinline__ ull f2_fma(ull a, ull b, ull c) {
    ull d; asm("fma.rn.f32x2 %0, %1, %2, %3;" : "=l"(d) : "l"(a), "l"(b), "l"(c)); return d;
}
__device__ __forceinline__ ull f2_mul(ull a, ull b) {
    ull d; asm("mul.rn.f32x2 %0, %1, %2;" : "=l"(d) : "l"(a), "l"(b)); return d;
}
__device__ __forceinline__ ull f2_add(ull a, ull b) {
    ull d; asm("add.rn.f32x2 %0, %1, %2;" : "=l"(d) : "l"(a), "l"(b)); return d;
}
__device__ __forceinline__ ull f2_pack(float lo, float hi) {
    ull d; asm("mov.b64 %0, {%1, %2};" : "=l"(d) : "f"(lo), "f"(hi)); return d;
}
__device__ __forceinline__ float2 f2_unpack(ull a) {
    float lo, hi; asm("mov.b64 {%0, %1}, %2;" : "=f"(lo), "=f"(hi) : "l"(a));
    return make_float2(lo, hi);
}
__device__ __forceinline__ float frcp(float x) {
    float r; asm("rcp.approx.f32 %0, %1;" : "=f"(r) : "f"(x)); return r;
}

// complex helpers
__device__ __forceinline__ float2 cmul(float2 a, float2 b) {
    return make_float2(a.x * b.x - a.y * b.y, a.x * b.y + a.y * b.x);
}
__device__ __forceinline__ float2 csq(float2 a) {
    return make_float2(a.x * a.x - a.y * a.y, 2.0f * a.x * a.y);
}
__device__ __forceinline__ float2 cadd(float2 a, float2 b) { return make_float2(a.x + b.x, a.y + b.y); }
__device__ __forceinline__ float2 csub(float2 a, float2 b) { return make_float2(a.x - b.x, a.y - b.y); }
__device__ __forceinline__ float2 cmuli(float2 a) { return make_float2(-a.y, a.x); }

// ============================================================================
// Kernel A: Cauchy sums. grid (HH, 4), block 128. 4 bins/thread.
// Inner loop uses numerator-expanded form:
//   re    = (pm + y2*qcp)   * inv
//   im/y  = (qmnpc - y2*q)  * inv,  inv = 1/((m-y2)^2 + c2*y2)
// ============================================================================
__global__ __launch_bounds__(128) void s4_cauchy(
    const float* __restrict__ A_real,
    const float* __restrict__ A_imag,
    const float* __restrict__ Bm,
    const float* __restrict__ Cm,
    const float* __restrict__ Pm,
    const float* __restrict__ inv_dt)
{
    __shared__ ulonglong2 s_coef[NN / 2][9];

    const int h   = blockIdx.x;
    const int tid = threadIdx.x;

    if (blockIdx.y == 0 && blockIdx.x < 9) {
        const int j = blockIdx.x * 128 + tid;
        if (j <= 1024) {
            float s, c;
            sincosf((float)j * (3.14159265358979323846f / 2048.0f), &s, &c);
            g_tw[j] = make_float2(c, s);
        }
    }

    if (tid < NN) {
        const int n  = tid;
        const float dt = expf(inv_dt[h]);
        const float ar = -expf(A_real[h * NN + n]) * dt;
        const float ai =  A_imag[h * NN + n] * dt;

        const int base = (h * NN + n) * 2;
        const float bx = Bm[base], by = Bm[base + 1];
        const float cx = Cm[base], cy = Cm[base + 1];
        const float px = Pm[base], py = Pm[base + 1];

        float vr[4], vi[4];
        vr[0] = (bx * cx - by * cy) * dt;  vi[0] = (bx * cy + by * cx) * dt;
        vr[1] = (bx * px + by * py) * dt;  vi[1] = (by * px - bx * py) * dt;
        vr[2] = (px * cx - py * cy) * dt;  vi[2] = (px * cy + py * cx) * dt;
        vr[3] = (px * px + py * py) * dt;  vi[3] = 0.0f;

        float* c = (float*)&s_coef[n >> 1][0];
        const int o = n & 1;
        const float ccoef = -2.0f * ar;
        const float m  = ar * ar + ai * ai;
        c[0 + o] = m;                              // m
        c[2 + o] = ccoef * ccoef;                  // c^2
        #pragma unroll
        for (int ab = 0; ab < 4; ab++) {
            const float p   = -2.0f * (vr[ab] * ar + vi[ab] * ai);
            const float q   =  2.0f * vr[ab];
            const float qc  = q * ccoef;
            const float npc = -p * ccoef;
            const int bo = 4 + ab * 8;
            c[bo + 0 + o] = p * m;                 // pm
            c[bo + 2 + o] = qc - p;                // qcp
            c[bo + 4 + o] = q * m + npc;           // qmnpc
            c[bo + 6 + o] = q;                     // q
        }
    }
    __syncthreads();

    const float ANG = 3.14159265358979323846f / 4096.0f;
    const int base_l = blockIdx.y * 512 + tid;

    float yv[4];
    ull y2v[4], ny2v[4];
    #pragma unroll
    for (int b = 0; b < 4; b++) {
        const float ang = (float)(base_l + b * 128) * ANG;
        float s_, c_;
        __sincosf(ang, &s_, &c_);
        const float y = 2.0f * s_ * frcp(c_);      // fast tan (MUFU path)
        yv[b] = y;
        y2v[b]  = f2_pack(y * y, y * y);
        ny2v[b] = y2v[b] ^ 0x8000000080000000ULL;
    }

    ull accr[4][4], acci[4][4];
    #pragma unroll
    for (int b = 0; b < 4; b++)
        #pragma unroll
        for (int ab = 0; ab < 4; ab++) { accr[b][ab] = 0; acci[b][ab] = 0; }

    #pragma unroll 4
    for (int k = 0; k < NN / 2; k++) {
        const ulonglong2* cc = &s_coef[k][0];
        const ulonglong2 c0 = cc[0];               // (m, c2)

        ull invv[4];
        #pragma unroll
        for (int b = 0; b < 4; b++) {
            const ull dr  = f2_add(c0.x, ny2v[b]);                 // m - y2
            const ull mag = f2_fma(dr, dr, f2_mul(c0.y, y2v[b]));  // dr^2 + c2*y2
            const float2 m = f2_unpack(mag);
            invv[b] = f2_pack(frcp(m.x), frcp(m.y));
        }

        #pragma unroll
        for (int ab = 0; ab < 4; ab++) {
            const ulonglong2 ca = cc[1 + 2 * ab];  // (pm, qcp)
            const ulonglong2 cb = cc[2 + 2 * ab];  // (qmnpc, q)
            #pragma unroll
            for (int b = 0; b < 4; b++) {
                const ull rt  = f2_fma(y2v[b],  ca.y, ca.x);   // pm + y2*qcp
                const ull it2 = f2_fma(ny2v[b], cb.y, cb.x);   // qmnpc - y2*q
                accr[b][ab] = f2_fma(rt,  invv[b], accr[b][ab]);
                acci[b][ab] = f2_fma(it2, invv[b], acci[b][ab]);
            }
        }
    }

    #pragma unroll
    for (int b = 0; b < 4; b++) {
        const float y = yv[b];
        const int   l = base_l + b * 128;
        const float2 sr0 = f2_unpack(accr[b][0]), si0 = f2_unpack(acci[b][0]);
        const float2 sr1 = f2_unpack(accr[b][1]), si1 = f2_unpack(acci[b][1]);
        const float2 sr2 = f2_unpack(accr[b][2]), si2 = f2_unpack(acci[b][2]);
        const float2 sr3 = f2_unpack(accr[b][3]), si3 = f2_unpack(acci[b][3]);
        const float r00r = sr0.x + sr0.y, r00i = (si0.x + si0.y) * y;
        const float r01r = sr1.x + sr1.y, r01i = (si1.x + si1.y) * y;
        const float r10r = sr2.x + sr2.y, r10i = (si2.x + si2.y) * y;
        const float r11r = sr3.x + sr3.y, r11i = (si3.x + si3.y) * y;

        const float cr = 1.0f + r11r, ci = r11i;
        const float cinv = frcp(cr * cr + ci * ci);
        const float trm = r01r * r10r - r01i * r10i;
        const float tim = r01r * r10i + r01i * r10r;
        const float qr = (trm * cr + tim * ci) * cinv;
        const float qi = (tim * cr - trm * ci) * cinv;
        const float kr = r00r - qr;
        const float ki = r00i - qi;
        const float hy = 0.5f * y;
        float fr = kr - ki * hy;
        float fi = ki + kr * hy;
        if (l == 0) fi = 0.0f;
        g_X[h * LF + l] = make_float2(fr, fi);
    }

    if (blockIdx.y == 3 && tid == 0) {
        const float y  = 2.0f * tanf(2048.0f * ANG);
        const float y2 = y * y;
        float rr[4] = {0, 0, 0, 0}, riy[4] = {0, 0, 0, 0};
        for (int n = 0; n < NN; n++) {
            const float* c = (const float*)&s_coef[n >> 1][0];
            const int o = n & 1;
            const float dr = c[0 + o] - y2;
            const float inv = frcp(dr * dr + c[2 + o] * y2);
            #pragma unroll
            for (int ab = 0; ab < 4; ab++) {
                const int bo = 4 + ab * 8;
                rr[ab]  += (c[bo + 0 + o] + y2 * c[bo + 2 + o]) * inv;
                riy[ab] += (c[bo + 4 + o] - y2 * c[bo + 6 + o]) * inv;
            }
        }
        const float r00r = rr[0];
        const float r01r = rr[1], r01i = riy[1] * y;
        const float r10r = rr[2], r10i = riy[2] * y;
        const float r11r = rr[3], r11i = riy[3] * y;
        const float cr = 1.0f + r11r, ci = r11i;
        const float cinv = frcp(cr * cr + ci * ci);
        const float trm = r01r * r10r - r01i * r10i;
        const float tim = r01r * r10i + r01i * r10r;
        const float qr = (trm * cr + tim * ci) * cinv;
        const float qi = (tim * cr - trm * ci) * cinv;
        const float kr = r00r - qr;
        const float ki = riy[0] * y - qi;
        const float fr = kr - ki * (0.5f * y);
        g_X[h * LF + 2048] = make_float2(fr, 0.0f);
    }
}

// ============================================================================
// Kernel B: irfft-4096 via complex iFFT-2048, radix-8, 8 elem/thread,
// aliased smem buffer. grid HH, block 256.
// ============================================================================
#define IDX(i) ((i) + ((i) >> 3))
#define R2C 0.70710678118654752f

__device__ __forceinline__ void radix8_pass(float2* spec, const float2* tw, int tid, int s) {
    const int hh   = 1 << (s - 1);
    const int j    = tid & (hh - 1);
    const int base = ((tid >> (s - 1)) << (s + 2)) + j;

    float2 x[8];
    #pragma unroll
    for (int q = 0; q < 8; q++) x[q] = spec[IDX(base + q * hh)];

    const float2 w4 = tw[j << (10 - s)];   // W_M^(j*2^(9-s))
    const float2 w2 = csq(w4);
    const float2 w1 = csq(w2);

    float2 a[8];
    #pragma unroll
    for (int p = 0; p < 4; p++) {
        const float2 t = cmul(w1, x[2 * p + 1]);
        a[2 * p]     = cadd(x[2 * p], t);
        a[2 * p + 1] = csub(x[2 * p], t);
    }
    float2 b[8];
    #pragma unroll
    for (int g = 0; g < 2; g++) {
        const int o = 4 * g;
        const float2 t2 = cmul(w2, a[o + 2]);
        const float2 t3 = cmuli(cmul(w2, a[o + 3]));
        b[o + 0] = cadd(a[o + 0], t2);
        b[o + 2] = csub(a[o + 0], t2);
        b[o + 1] = cadd(a[o + 1], t3);
        b[o + 3] = csub(a[o + 1], t3);
    }
    const float2 u  = make_float2(R2C, R2C);
    const float2 vu = cmul(w4, u);
    const float2 t4 = cmul(w4, b[4]);
    const float2 t5 = cmul(vu, b[5]);
    const float2 t6 = cmul(cmuli(w4), b[6]);
    const float2 t7 = cmul(cmuli(vu), b[7]);

    spec[IDX(base + 0 * hh)] = cadd(b[0], t4);
    spec[IDX(base + 4 * hh)] = csub(b[0], t4);
    spec[IDX(base + 1 * hh)] = cadd(b[1], t5);
    spec[IDX(base + 5 * hh)] = csub(b[1], t5);
    spec[IDX(base + 2 * hh)] = cadd(b[2], t6);
    spec[IDX(base + 6 * hh)] = csub(b[2], t6);
    spec[IDX(base + 3 * hh)] = cadd(b[3], t7);
    spec[IDX(base + 7 * hh)] = csub(b[3], t7);
}

__global__ __launch_bounds__(256) void s4_fft(float* __restrict__ out)
{
    __shared__ float2 buf[2305];    // X staging, then FFT workspace (aliased)
    __shared__ float2 tw[1025];

    const int h   = blockIdx.x;
    const int tid = threadIdx.x;

    const float2* Xh = &g_X[h * LF];
    #pragma unroll
    for (int m = 0; m < 8; m++) {
        const int i = tid + m * 256;
        buf[IDX(i)] = Xh[i];
    }
    if (tid == 0) buf[IDX(2048)] = Xh[2048];
    for (int j = tid; j <= 1024; j += 256) tw[j] = g_tw[j];
    __syncthreads();

    // gather X (bit-reversed), build Z, in-register radix-8 (stages 1-3)
    {
        const int rv = __brev(tid) >> 24;             // rev8(tid)
        float2 c[8];
        #pragma unroll
        for (int q = 0; q < 8; q++) {
            const int rq = (q == 0) ? 0 : (q == 1) ? 4 : (q == 2) ? 2 : (q == 3) ? 6
                         : (q == 4) ? 1 : (q == 5) ? 5 : (q == 6) ? 3 : 7;   // rev3(q)
            const int k  = rq * 256 + rv;
            const float2 Xk = buf[IDX(k)];
            const float2 Xm = buf[IDX(2048 - k)];
            float2 w;
            if (k <= 1024) w = tw[k];
            else { const float2 t = tw[k - 1024]; w = make_float2(-t.y, t.x); }
            const float arr = Xk.x + Xm.x, aii = Xk.y - Xm.y;
            const float brr = Xk.x - Xm.x, bii = Xk.y + Xm.y;
            c[q] = make_float2(arr - (w.x * bii + w.y * brr),
                               aii + (w.x * brr - w.y * bii));
        }
        float2 a[8];
        #pragma unroll
        for (int p = 0; p < 4; p++) {
            a[2 * p]     = cadd(c[2 * p], c[2 * p + 1]);
            a[2 * p + 1] = csub(c[2 * p], c[2 * p + 1]);
        }
        float2 b[8];
        #pragma unroll
        for (int g = 0; g < 2; g++) {
            const int o = 4 * g;
            const float2 t3 = cmuli(a[o + 3]);
            b[o + 0] = cadd(a[o + 0], a[o + 2]);
            b[o + 2] = csub(a[o + 0], a[o + 2]);
            b[o + 1] = cadd(a[o + 1], t3);
            b[o + 3] = csub(a[o + 1], t3);
        }
        const float2 t4 = b[4];
        const float2 t5 = make_float2(R2C * (b[5].x - b[5].y), R2C * (b[5].x + b[5].y));
        const float2 t6 = cmuli(b[6]);
        const float2 t7 = make_float2(-R2C * (b[7].x + b[7].y), R2C * (b[7].x - b[7].y));

        __syncthreads();    // everyone done READING buf before overwriting it

        const int p0 = 8 * tid;
        buf[IDX(p0 + 0)] = cadd(b[0], t4);
        buf[IDX(p0 + 4)] = csub(b[0], t4);
        buf[IDX(p0 + 1)] = cadd(b[1], t5);
        buf[IDX(p0 + 5)] = csub(b[1], t5);
        buf[IDX(p0 + 2)] = cadd(b[2], t6);
        buf[IDX(p0 + 6)] = csub(b[2], t6);
        buf[IDX(p0 + 3)] = cadd(b[3], t7);
        buf[IDX(p0 + 7)] = csub(b[3], t7);
    }
    __syncthreads();

    radix8_pass(buf, tw, tid, 4);    // stages 4,5,6
    __syncthreads();
    radix8_pass(buf, tw, tid, 7);    // stages 7,8,9
    __syncthreads();

    // stages 10,11: fused radix-4, 512 butterflies, 2 per thread
    #pragma unroll
    for (int m = 0; m < 2; m++) {
        const int j = tid + m * 256;
        const float2 w2 = tw[2 * j];          // W_M^j
        const float2 w1 = csq(w2);
        const float2 x0 = buf[IDX(j)];
        const float2 x1 = buf[IDX(j + 512)];
        const float2 x2 = buf[IDX(j + 1024)];
        const float2 x3 = buf[IDX(j + 1536)];
        const float2 t1 = cmul(w1, x1);
        const float2 a0 = cadd(x0, t1), a1 = csub(x0, t1);
        const float2 t3 = cmul(w1, x3);
        const float2 a2 = cadd(x2, t3), a3 = csub(x2, t3);
        const float2 t2 = cmul(w2, a2);
        const float2 c3 = cmuli(cmul(w2, a3));
        buf[IDX(j)]        = cadd(a0, t2);
        buf[IDX(j + 1024)] = csub(a0, t2);
        buf[IDX(j + 512)]  = cadd(a1, c3);
        buf[IDX(j + 1536)] = csub(a1, c3);
    }
    __syncthreads();

    float2* out2 = (float2*)(out + h * LL);
    const float scale = 1.0f / (float)LL;
    #pragma unroll
    for (int m = 0; m < 8; m++) {
        const int n = tid + m * 256;
        const float2 z = buf[IDX(n)];
        out2[n] = make_float2(z.x * scale, z.y * scale);
    }
}

extern "C" void kernel_launch(void* const* d_in, const int* in_sizes, int n_in,
                              void* d_out, int out_size)
{
    (void)in_sizes; (void)n_in; (void)out_size;
    dim3 gridA(HH, 4);
    s4_cauchy<<<gridA, 128>>>(
        (const float*)d_in[0],   // A_real (H, N)
        (const float*)d_in[1],   // A_imag (H, N)
        (const float*)d_in[2],   // B (1, H, N, 2)
        (const float*)d_in[3],   // C (1, H, N, 2)
        (const float*)d_in[4],   // P (1, H, N, 2)
        (const float*)d_in[5]);  // inv_dt (H,)
    s4_fft<<<HH, 256>>>((float*)d_out);
}